// round 16
// baseline (speedup 1.0000x reference)
#include <cuda_runtime.h>
#include <cuda_bf16.h>

#define NN   100000
#define EE   1600000
#define ET   (EE + NN)
#define HID  128
#define NT   64                 // nodes per block (node kernels)
#define XS   136                // bf16 activation row stride (k=128 + pad)
#define SCB  100                // scan blocks
#define SCL  1000               // nodes per scan block

// ---------------- scratch globals --------------------------------------------
__device__ __align__(16) __nv_bfloat16 g_xw1b[(size_t)NN * HID]; // xw1 bf16
__device__ __align__(16) __nv_bfloat16 g_xw2b[(size_t)NN * HID]; // xw2 bf16
__device__ __align__(16) float g_es1 [NN * 4];
__device__ __align__(16) float g_ed1 [NN * 4];
__device__ __align__(16) float g_out1[(size_t)NN * HID];
__device__ __align__(16) float g_es2 [NN];
__device__ __align__(16) float g_ed2 [NN];
__device__ __align__(16) float g_out2[(size_t)NN * HID];

// fragment-packed weights: [col][kstep][quad] -> 16B {hi01,hi89,lo01,lo89}
__device__ __align__(16) __nv_bfloat16 g_W1p [64 * 48 * 4 * 8];
__device__ __align__(16) __nv_bfloat16 g_Wip [128 * 8 * 4 * 8];
__device__ __align__(16) __nv_bfloat16 g_g1p [128 * 8 * 4 * 8];
__device__ __align__(16) __nv_bfloat16 g_g2p [128 * 8 * 4 * 8];
__device__ __align__(16) __nv_bfloat16 g_Wo1p[128 * 8 * 4 * 8];

// CSR (dst-grouped)
__device__ int g_cnt[NN];
__device__ int g_rs [NN + 1];
__device__ int g_cur[NN];
__device__ int g_csrc[ET];
__device__ int g_part[SCB];

__device__ __forceinline__ float lrelu01(float v) { return v > 0.f ? v : 0.01f * v; }
__device__ __forceinline__ float lrelu2 (float v) { return v > 0.f ? v : 0.2f  * v; }

__device__ __forceinline__ unsigned cvta_s(const void* p) {
    return (unsigned)__cvta_generic_to_shared(p);
}
__device__ __forceinline__ void ldm_x4(uint4& v, unsigned addr) {
    asm volatile("ldmatrix.sync.aligned.m8n8.x4.shared.b16 {%0,%1,%2,%3}, [%4];"
                 : "=r"(v.x), "=r"(v.y), "=r"(v.z), "=r"(v.w) : "r"(addr));
}
__device__ __forceinline__ void mma_bf16(float c[4], const uint4& a,
                                         unsigned b0, unsigned b1) {
    asm volatile(
        "mma.sync.aligned.m16n8k16.row.col.f32.bf16.bf16.f32 "
        "{%0,%1,%2,%3},{%4,%5,%6,%7},{%8,%9},{%0,%1,%2,%3};"
        : "+f"(c[0]), "+f"(c[1]), "+f"(c[2]), "+f"(c[3])
        : "r"(a.x), "r"(a.y), "r"(a.z), "r"(a.w), "r"(b0), "r"(b1));
}

// f32x2 -> bf16x2 hi + lo
__device__ __forceinline__ void cvt2(float2 v, unsigned& h, unsigned& l) {
    __nv_bfloat162 hb = __float22bfloat162_rn(v);
    h = *(unsigned*)&hb;
    const float2 hf = __bfloat1622float2(hb);
    __nv_bfloat162 lb = __float22bfloat162_rn(make_float2(v.x - hf.x, v.y - hf.y));
    l = *(unsigned*)&lb;
}
__device__ __forceinline__ void split4(float4 v, uint2& h, uint2& l) {
    cvt2(make_float2(v.x, v.y), h.x, l.x);
    cvt2(make_float2(v.z, v.w), h.y, l.y);
}
__device__ __forceinline__ unsigned pack_bf2(float a, float b) {
    __nv_bfloat162 t = __halves2bfloat162(__float2bfloat16(a), __float2bfloat16(b));
    return *(unsigned*)&t;
}
__device__ __forceinline__ float2 bf2f(unsigned u) {
    float2 r;
    r.x = __uint_as_float(u << 16);
    r.y = __uint_as_float(u & 0xffff0000u);
    return r;
}

// 3-term bf16 GEMM: MT*16 nodes x 32 cols (per warp) x K=128.
template <int MT>
__device__ __forceinline__ void mma_gemmT(const __nv_bfloat16* abuf,
                                          const __nv_bfloat16* __restrict__ wp,
                                          int wid, int lane, float c[MT][4][4]) {
    const int row_l = (lane & 7) + ((lane >> 3) & 1) * 8;
    const int koff  = (lane >> 4) * 8;
    const int nrow  = lane >> 2, q = lane & 3;
    const unsigned sb = cvta_s(abuf);
    const int LO = MT * 16;
#pragma unroll
    for (int ks = 0; ks < 8; ks++) {
        uint4 ah[MT], al[MT];
#pragma unroll
        for (int m = 0; m < MT; m++) {
            ldm_x4(ah[m], sb + ((m * 16 + row_l) * XS + ks * 16 + koff) * 2);
            ldm_x4(al[m], sb + ((LO + m * 16 + row_l) * XS + ks * 16 + koff) * 2);
        }
#pragma unroll
        for (int nt = 0; nt < 4; nt++) {
            const int col = wid * 32 + nt * 8 + nrow;
            const uint4 b = *(const uint4*)(wp + ((size_t)(col * 8 + ks) * 4 + q) * 8);
#pragma unroll
            for (int m = 0; m < MT; m++) {
                mma_bf16(c[m][nt], ah[m], b.x, b.y);
                mma_bf16(c[m][nt], ah[m], b.z, b.w);
                mma_bf16(c[m][nt], al[m], b.x, b.y);
            }
        }
    }
}

// ---------------- weight prep + cnt init --------------------------------------
__device__ __forceinline__ uint4 pack_frag(float v0, float v1, float v2, float v3) {
    uint4 r; uint2 h, l;
    cvt2(make_float2(v0, v1), h.x, l.x);
    cvt2(make_float2(v2, v3), h.y, l.y);
    r.x = h.x; r.y = h.y; r.z = l.x; r.w = l.y;
    return r;
}

__global__ void k_wprep(const float* __restrict__ Wd, const float* __restrict__ Wt,
                        const float* __restrict__ Wi, const float* __restrict__ g1W,
                        const float* __restrict__ g2W, const float* __restrict__ Wo1) {
    const int i = blockIdx.x * blockDim.x + threadIdx.x;
    if (i < NN) g_cnt[i] = 1;
    if (i < 64 * 48 * 4) {
        const int col = i / 192, ks = (i % 192) / 4, q = i % 4;
        const int k0 = ks * 16 + q * 2;
        const float* src = (col < 32) ? Wd + (size_t)col * 768
                                      : Wt + (size_t)(col - 32) * 768;
        *(uint4*)(g_W1p + (size_t)i * 8) =
            pack_frag(src[k0], src[k0 + 1], src[k0 + 8], src[k0 + 9]);
    } else if (i < 64 * 48 * 4 + 4 * 128 * 8 * 4) {
        const int j = i - 64 * 48 * 4;
        const int mat = j >> 12, r = j & 4095;
        const int col = r / 32, ks = (r % 32) / 4, q = r % 4;
        const int k0 = ks * 16 + q * 2;
        const float* W = (mat == 0 ? Wi : mat == 1 ? g1W : mat == 2 ? g2W : Wo1)
                       + (size_t)col * 128;
        __nv_bfloat16* dst = (mat == 0 ? g_Wip : mat == 1 ? g_g1p
                              : mat == 2 ? g_g2p : g_Wo1p);
        *(uint4*)(dst + (size_t)r * 8) =
            pack_frag(W[k0], W[k0 + 1], W[k0 + 8], W[k0 + 9]);
    }
}

// ---------------- CSR build ---------------------------------------------------
__global__ void k_count(const int* __restrict__ ei) {
    int i = blockIdx.x * blockDim.x + threadIdx.x;
    if (i < EE) atomicAdd(&g_cnt[ei[EE + i]], 1);
}
__global__ void k_scan1() {
    __shared__ int sh[256];
    const int b = blockIdx.x, t = threadIdx.x;
    const int base = b * SCL;
    int s = 0;
    for (int i = t; i < SCL; i += 256) s += g_cnt[base + i];
    sh[t] = s;
    __syncthreads();
    for (int o = 128; o > 0; o >>= 1) {
        if (t < o) sh[t] += sh[t + o];
        __syncthreads();
    }
    if (t == 0) g_part[b] = sh[0];
}
__global__ void k_scan2() {
    if (threadIdx.x == 0) {
        int acc = 0;
        for (int i = 0; i < SCB; i++) { int v = g_part[i]; g_part[i] = acc; acc += v; }
        g_rs[NN] = ET;
    }
}
__global__ void k_scan3() {
    __shared__ int sh[256];
    const int b = blockIdx.x, t = threadIdx.x;
    const int base = b * SCL;
    int loc[4];
    int s = 0;
#pragma unroll
    for (int j = 0; j < 4; j++) {
        const int idx = t * 4 + j;
        loc[j] = (idx < SCL) ? g_cnt[base + idx] : 0;
        s += loc[j];
    }
    sh[t] = s;
    __syncthreads();
    for (int o = 1; o < 256; o <<= 1) {
        int v = (t >= o) ? sh[t - o] : 0;
        __syncthreads();
        sh[t] += v;
        __syncthreads();
    }
    int pre = g_part[b] + (t ? sh[t - 1] : 0);
#pragma unroll
    for (int j = 0; j < 4; j++) {
        const int idx = t * 4 + j;
        if (idx < SCL) {
            g_rs[base + idx] = pre;
            g_cur[base + idx] = pre;
            pre += loc[j];
        }
    }
}
__global__ void k_fill(const int* __restrict__ ei) {
    int i = blockIdx.x * blockDim.x + threadIdx.x;
    if (i >= ET) return;
    int src, dst;
    if (i < EE) { src = ei[i]; dst = ei[EE + i]; }
    else        { src = dst = i - EE; }
    g_csrc[atomicAdd(&g_cur[dst], 1)] = src;
}

// ---------------- features -> x -> Wi -> g1 projection + attn logits ---------
__global__ void __launch_bounds__(128, 4) k_features(
    const float* __restrict__ des, const float* __restrict__ twt,
    const float* __restrict__ npr, const float* __restrict__ cpr,
    const float* __restrict__ bd,  const float* __restrict__ bt,
    const float* __restrict__ Wn,  const float* __restrict__ bn,
    const float* __restrict__ Wc,  const float* __restrict__ bc,
    const float* __restrict__ bi,
    const float* __restrict__ g1as, const float* __restrict__ g1ad)
{
    __shared__ __align__(16) __nv_bfloat16 xb[128 * XS];   // hi rows 0-63, lo 64-127

    const int tid = threadIdx.x;
    const int n0  = blockIdx.x * NT;
    const int wid = tid >> 5, lane = tid & 31;
    const int lr = lane >> 2, lq = lane & 3, lq2 = lq * 2;

    // ---- stage 1: register-prefetched fragments, warp = (arr, node-half) ----
    const int arr = wid & 1;
    const int mh  = wid >> 1;            // nodes mh*32 .. mh*32+31

    float c1[2][4][4];
#pragma unroll
    for (int m = 0; m < 2; m++)
#pragma unroll
        for (int nt = 0; nt < 4; nt++)
#pragma unroll
            for (int q = 0; q < 4; q++) c1[m][nt][q] = 0.f;

    {
        const float* A = arr ? twt : des;
        const float* rp[2][2];
#pragma unroll
        for (int m = 0; m < 2; m++) {
            int r0 = n0 + mh * 32 + m * 16 + lr;
            int r1 = r0 + 8;
            if (r0 >= NN) r0 = NN - 1;
            if (r1 >= NN) r1 = NN - 1;
            rp[m][0] = A + (size_t)r0 * 768 + lq2;
            rp[m][1] = A + (size_t)r1 * 768 + lq2;
        }
        // prefetch chunk 0
        float2 cur[2][4];
#pragma unroll
        for (int m = 0; m < 2; m++) {
            cur[m][0] = *(const float2*)(rp[m][0]);
            cur[m][1] = *(const float2*)(rp[m][1]);
            cur[m][2] = *(const float2*)(rp[m][0] + 8);
            cur[m][3] = *(const float2*)(rp[m][1] + 8);
        }
#pragma unroll 2
        for (int ks = 0; ks < 48; ks++) {
            float2 nxt[2][4];
            if (ks < 47) {
                const int kk = (ks + 1) * 16;
#pragma unroll
                for (int m = 0; m < 2; m++) {
                    nxt[m][0] = *(const float2*)(rp[m][0] + kk);
                    nxt[m][1] = *(const float2*)(rp[m][1] + kk);
                    nxt[m][2] = *(const float2*)(rp[m][0] + kk + 8);
                    nxt[m][3] = *(const float2*)(rp[m][1] + kk + 8);
                }
            }
            uint4 ah[2], al[2];
#pragma unroll
            for (int m = 0; m < 2; m++) {
                cvt2(cur[m][0], ah[m].x, al[m].x);
                cvt2(cur[m][1], ah[m].y, al[m].y);
                cvt2(cur[m][2], ah[m].z, al[m].z);
                cvt2(cur[m][3], ah[m].w, al[m].w);
            }
#pragma unroll
            for (int nt = 0; nt < 4; nt++) {
                const int col = arr * 32 + nt * 8 + lr;
                const uint4 b = *(const uint4*)(g_W1p +
                    ((size_t)(col * 48 + ks) * 4 + lq) * 8);
#pragma unroll
                for (int m = 0; m < 2; m++) {
                    mma_bf16(c1[m][nt], ah[m], b.x, b.y);
                    mma_bf16(c1[m][nt], ah[m], b.z, b.w);
                    mma_bf16(c1[m][nt], al[m], b.x, b.y);
                }
            }
#pragma unroll
            for (int m = 0; m < 2; m++) {
                cur[m][0] = nxt[m][0]; cur[m][1] = nxt[m][1];
                cur[m][2] = nxt[m][2]; cur[m][3] = nxt[m][3];
            }
        }
    }

    // ---- stage-1 epilogue: bias + lrelu -> xb hi/lo [node][col] -------------
#pragma unroll
    for (int m = 0; m < 2; m++)
#pragma unroll
        for (int nt = 0; nt < 4; nt++) {
            const int cb = arr * 32 + nt * 8 + lq2;
            const float b0 = (cb < 32) ? bd[cb] : bt[cb - 32];
            const float b1 = (cb + 1 < 32) ? bd[cb + 1] : bt[cb - 31];
            const int r0 = mh * 32 + m * 16 + lr;
            const float v00 = lrelu01(c1[m][nt][0] + b0), v01 = lrelu01(c1[m][nt][1] + b1);
            const float v10 = lrelu01(c1[m][nt][2] + b0), v11 = lrelu01(c1[m][nt][3] + b1);
            *(unsigned*)(xb + r0 * XS + cb)        = pack_bf2(v00, v01);
            *(unsigned*)(xb + (64 + r0) * XS + cb) = pack_bf2(
                v00 - __bfloat162float(__float2bfloat16(v00)),
                v01 - __bfloat162float(__float2bfloat16(v01)));
            *(unsigned*)(xb + (r0 + 8) * XS + cb)  = pack_bf2(v10, v11);
            *(unsigned*)(xb + (72 + r0) * XS + cb) = pack_bf2(
                v10 - __bfloat162float(__float2bfloat16(v10)),
                v11 - __bfloat162float(__float2bfloat16(v11)));
        }
    {   // num/cat cols 64-127 over 64 nodes
        const int col = tid >> 1, nh = (tid & 1) * 32;
        if (col < 32) {
            const float w0 = Wn[col * 5], w1 = Wn[col * 5 + 1], w2 = Wn[col * 5 + 2],
                        w3 = Wn[col * 5 + 3], w4 = Wn[col * 5 + 4];
            const float b = bn[col];
            for (int m = 0; m < 32; m++) {
                int gr = n0 + nh + m; if (gr >= NN) gr = NN - 1;
                const float* r = npr + (size_t)gr * 5;
                const float v = lrelu01(r[0]*w0 + r[1]*w1 + r[2]*w2 + r[3]*w3 + r[4]*w4 + b);
                const __nv_bfloat16 h = __float2bfloat16(v);
                xb[(nh + m) * XS + 64 + col] = h;
                xb[(64 + nh + m) * XS + 64 + col] = __float2bfloat16(v - __bfloat162float(h));
            }
        } else {
            const int jj = col - 32;
            const float w0 = Wc[jj * 3], w1 = Wc[jj * 3 + 1], w2 = Wc[jj * 3 + 2];
            const float b = bc[jj];
            for (int m = 0; m < 32; m++) {
                int gr = n0 + nh + m; if (gr >= NN) gr = NN - 1;
                const float* r = cpr + (size_t)gr * 3;
                const float v = lrelu01(r[0]*w0 + r[1]*w1 + r[2]*w2 + b);
                const __nv_bfloat16 h = __float2bfloat16(v);
                xb[(nh + m) * XS + 96 + jj] = h;
                xb[(64 + nh + m) * XS + 96 + jj] = __float2bfloat16(v - __bfloat162float(h));
            }
        }
    }
    __syncthreads();

    // ---- stage 2: x2 = lrelu(x @ Wi^T + bi), write back into xb -------------
    {
        float c[4][4][4];
#pragma unroll
        for (int m = 0; m < 4; m++)
#pragma unroll
            for (int nt = 0; nt < 4; nt++)
#pragma unroll
                for (int q = 0; q < 4; q++) c[m][nt][q] = 0.f;
        mma_gemmT<4>(xb, g_Wip, wid, lane, c);
        __syncthreads();
#pragma unroll
        for (int m = 0; m < 4; m++)
#pragma unroll
            for (int nt = 0; nt < 4; nt++) {
                const int cb = wid * 32 + nt * 8 + lq2;
                const float b0 = bi[cb], b1 = bi[cb + 1];
                const int r0 = m * 16 + lr;
                const float v00 = lrelu01(c[m][nt][0] + b0), v01 = lrelu01(c[m][nt][1] + b1);
                const float v10 = lrelu01(c[m][nt][2] + b0), v11 = lrelu01(c[m][nt][3] + b1);
                *(unsigned*)(xb + r0 * XS + cb)        = pack_bf2(v00, v01);
                *(unsigned*)(xb + (64 + r0) * XS + cb) = pack_bf2(
                    v00 - __bfloat162float(__float2bfloat16(v00)),
                    v01 - __bfloat162float(__float2bfloat16(v01)));
                *(unsigned*)(xb + (r0 + 8) * XS + cb)  = pack_bf2(v10, v11);
                *(unsigned*)(xb + (72 + r0) * XS + cb) = pack_bf2(
                    v10 - __bfloat162float(__float2bfloat16(v10)),
                    v11 - __bfloat162float(__float2bfloat16(v11)));
            }
    }
    __syncthreads();

    // ---- stage 3: xw1 = x2 @ g1_W^T + per-head logits; xw1 stored bf16 ------
    {
        float c[4][4][4];
#pragma unroll
        for (int m = 0; m < 4; m++)
#pragma unroll
            for (int nt = 0; nt < 4; nt++)
#pragma unroll
                for (int q = 0; q < 4; q++) c[m][nt][q] = 0.f;
        mma_gemmT<4>(xb, g_g1p, wid, lane, c);

        float ps[4][2], pd[4][2];
#pragma unroll
        for (int m = 0; m < 4; m++) { ps[m][0]=ps[m][1]=pd[m][0]=pd[m][1]=0.f; }
#pragma unroll
        for (int m = 0; m < 4; m++)
#pragma unroll
            for (int nt = 0; nt < 4; nt++) {
                const int cb = wid * 32 + nt * 8 + lq2;
                const int node = n0 + m * 16 + lr;
                if (node < NN)
                    *(unsigned*)(g_xw1b + (size_t)node * HID + cb) =
                        pack_bf2(c[m][nt][0], c[m][nt][1]);
                if (node + 8 < NN)
                    *(unsigned*)(g_xw1b + (size_t)(node + 8) * HID + cb) =
                        pack_bf2(c[m][nt][2], c[m][nt][3]);
                const float a0 = g1as[cb], a1 = g1as[cb + 1];
                const float d0 = g1ad[cb], d1 = g1ad[cb + 1];
                ps[m][0] += c[m][nt][0]*a0 + c[m][nt][1]*a1;
                ps[m][1] += c[m][nt][2]*a0 + c[m][nt][3]*a1;
                pd[m][0] += c[m][nt][0]*d0 + c[m][nt][1]*d1;
                pd[m][1] += c[m][nt][2]*d0 + c[m][nt][3]*d1;
            }
#pragma unroll
        for (int m = 0; m < 4; m++)
#pragma unroll
            for (int rr = 0; rr < 2; rr++) {
#pragma unroll
                for (int o = 1; o < 4; o <<= 1) {
                    ps[m][rr] += __shfl_xor_sync(0xffffffffu, ps[m][rr], o);
                    pd[m][rr] += __shfl_xor_sync(0xffffffffu, pd[m][rr], o);
                }
            }
        if ((lane & 3) == 0) {
#pragma unroll
            for (int m = 0; m < 4; m++) {
                const int node = n0 + m * 16 + lr;
                if (node < NN) {
                    g_es1[node * 4 + wid] = ps[m][0];
                    g_ed1[node * 4 + wid] = pd[m][0];
                }
                if (node + 8 < NN) {
                    g_es1[(node + 8) * 4 + wid] = ps[m][1];
                    g_ed1[(node + 8) * 4 + wid] = pd[m][1];
                }
            }
        }
    }
}

// ---------------- GAT1 aggregation: dual-dst warps, bf16 gather ---------------
__global__ void __launch_bounds__(256) k_agg1(const float* __restrict__ g1b) {
    const int w = (blockIdx.x * blockDim.x + threadIdx.x) >> 5;
    const int lane = threadIdx.x & 31;
    const int d0 = 2 * w, d1 = 2 * w + 1;
    if (d0 >= NN) return;
    const int h = lane >> 3;
    int s0 = g_rs[d0];
    const int e0 = g_rs[d0 + 1];
    int s1 = (d1 < NN) ? e0 : 0;
    const int e1 = (d1 < NN) ? g_rs[d1 + 1] : 0;
    const float ev0d = g_ed1[d0 * 4 + h];
    const float ev1d = (d1 < NN) ? g_ed1[d1 * 4 + h] : 0.f;
    float4 a0 = {0,0,0,0}, a1 = {0,0,0,0};
    float den0 = 0.f, den1 = 0.f;
    while (s0 < e0 || s1 < e1) {
        const bool p0 = s0 < e0, p1 = s1 < e1;
        int i0 = 0, i1 = 0;
        if (p0) i0 = __ldg(&g_csrc[s0]);
        if (p1) i1 = __ldg(&g_csrc[s1]);
        if (p0) {
            const float es = __ldg(&g_es1[i0 * 4 + h]);
            const uint2 xs = *(const uint2*)(g_xw1b + (size_t)i0 * HID + lane * 4);
            const float ev = __expf(lrelu2(es + ev0d));
            const float2 f01 = bf2f(xs.x), f23 = bf2f(xs.y);
            a0.x += f01.x * ev; a0.y += f01.y * ev;
            a0.z += f23.x * ev; a0.w += f23.y * ev;
            den0 += ev;
            s0++;
        }
        if (p1) {
            const float es = __ldg(&g_es1[i1 * 4 + h]);
            const uint2 xs = *(const uint2*)(g_xw1b + (size_t)i1 * HID + lane * 4);
            const float ev = __expf(lrelu2(es + ev1d));
            const float2 f01 = bf2f(xs.x), f23 = bf2f(xs.y);
            a1.x += f01.x * ev; a1.y += f01.y * ev;
            a1.z += f23.x * ev; a1.w += f23.y * ev;
            den1 += ev;
            s1++;
        }
    }
    const float4 b = ((const float4*)g1b)[lane];
    {
        const float inv = 1.f / den0;
        float4 o;
        o.x = a0.x * inv + b.x; o.y = a0.y * inv + b.y;
        o.z = a0.z * inv + b.z; o.w = a0.w * inv + b.w;
        *(float4*)(g_out1 + (size_t)d0 * HID + lane * 4) = o;
    }
    if (d1 < NN) {
        const float inv = 1.f / den1;
        float4 o;
        o.x = a1.x * inv + b.x; o.y = a1.y * inv + b.y;
        o.z = a1.z * inv + b.z; o.w = a1.w * inv + b.w;
        *(float4*)(g_out1 + (size_t)d1 * HID + lane * 4) = o;
    }
}

// ---------------- GAT2 projection + attn logits -------------------------------
__global__ void __launch_bounds__(128) k_gat2_prep(
    const float* __restrict__ g2as, const float* __restrict__ g2ad)
{
    __shared__ __align__(16) __nv_bfloat16 ab[128 * XS];
    __shared__ float sp[2][4][NT];
    const int tid = threadIdx.x, n0 = blockIdx.x * NT;
    const int wid = tid >> 5, lane = tid & 31;
    const int lr = lane >> 2, lq2 = (lane & 3) * 2;

    for (int i = 0; i < 16; i++) {
        const int idx = tid + i * 128;
        const int node = idx >> 5, c4 = idx & 31;
        int gr = n0 + node; if (gr >= NN) gr = NN - 1;
        const float4 v = *(const float4*)(g_out1 + (size_t)gr * HID + 4 * c4);
        uint2 h, l;
        split4(v, h, l);
        *(uint2*)(ab + node * XS + 4 * c4) = h;
        *(uint2*)(ab + (64 + node) * XS + 4 * c4) = l;
    }
    __syncthreads();

    float c[4][4][4];
#pragma unroll
    for (int m = 0; m < 4; m++)
#pragma unroll
        for (int nt = 0; nt < 4; nt++)
#pragma unroll
            for (int q = 0; q < 4; q++) c[m][nt][q] = 0.f;
    mma_gemmT<4>(ab, g_g2p, wid, lane, c);

    float ps[4][2], pd[4][2];
#pragma unroll
    for (int m = 0; m < 4; m++) { ps[m][0]=ps[m][1]=pd[m][0]=pd[m][1]=0.f; }
#pragma unroll
    for (int m = 0; m < 4; m++)
#pragma unroll
        for (int nt = 0; nt < 4; nt++) {
            const int cb = wid * 32 + nt * 8 + lq2;
            const int node = n0 + m * 16 + lr;
            if (node < NN)
                *(unsigned*)(g_xw2b + (size_t)node * HID + cb) =
                    pack_bf2(c[m][nt][0], c[m][nt][1]);
            if (node + 8 < NN)
                *(unsigned*)(g_xw2b + (size_t)(node + 8) * HID + cb) =
                    pack_bf2(c[m][nt][2], c[m][nt][3]);
            const float a0 = g2as[cb], a1 = g2as[cb + 1];
            const float d0 = g2ad[cb], d1 = g2ad[cb + 1];
            ps[m][0] += c[m][nt][0]*a0 + c[m][nt][1]*a1;
            ps[m][1] += c[m][nt][2]*a0 + c[m][nt][3]*a1;
            pd[m][0] += c[m][nt][0]*d0 + c[m][nt][1]*d1;
            pd[m][1] += c[m][nt][2]*d0 + c[m][nt][3]*d1;
        }
#pragma unroll
    for (int m = 0; m < 4; m++)
#pragma unroll
        for (int rr = 0; rr < 2; rr++) {
#pragma unroll
            for (int o = 1; o < 4; o <<= 1) {
                ps[m][rr] += __shfl_xor_sync(0xffffffffu, ps[m][rr], o);
                pd[m][rr] += __shfl_xor_sync(0xffffffffu, pd[m][rr], o);
            }
        }
    if ((lane & 3) == 0) {
#pragma unroll
        for (int m = 0; m < 4; m++) {
            sp[0][wid][m * 16 + lr]     = ps[m][0];
            sp[0][wid][m * 16 + lr + 8] = ps[m][1];
            sp[1][wid][m * 16 + lr]     = pd[m][0];
            sp[1][wid][m * 16 + lr + 8] = pd[m][1];
        }
    }
    __syncthreads();
    if (tid < NT) {
        if (n0 + tid < NN)
            g_es2[n0 + tid] = sp[0][0][tid] + sp[0][1][tid] + sp[0][2][tid] + sp[0][3][tid];
    } else {
        const int m = tid - NT;
        if (n0 + m < NN)
            g_ed2[n0 + m] = sp[1][0][m] + sp[1][1][m] + sp[1][2][m] + sp[1][3][m];
    }
}

// ---------------- GAT2 aggregation: dual-dst warps ----------------------------
__global__ void __launch_bounds__(256) k_agg2(const float* __restrict__ g2b) {
    const int w = (blockIdx.x * blockDim.x + threadIdx.x) >> 5;
    const int lane = threadIdx.x & 31;
    const int d0 = 2 * w, d1 = 2 * w + 1;
    if (d0 >= NN) return;
    int s0 = g_rs[d0];
    const int e0 = g_rs[d0 + 1];
    int s1 = (d1 < NN) ? e0 : 0;
    const int e1 = (d1 < NN) ? g_rs[d1 + 1] : 0;
    const float ev0d = g_ed2[d0];
    const float ev1d = (d1 < NN) ? g_ed2[d1] : 0.f;
    float4 a0 = {0,0,0,0}, a1 = {0,0,0,0};
    float den0 = 0.f, den1 = 0.f;
    while (s0 < e0 || s1 < e1) {
        const bool p0 = s0 < e0, p1 = s1 < e1;
        int i0 = 0, i1 = 0;
        if (p0) i0 = __ldg(&g_csrc[s0]);
        if (p1) i1 = __ldg(&g_csrc[s1]);
        if (p0) {
            const float es = __ldg(&g_es2[i0]);
            const uint2 xs = *(const uint2*)(g_xw2b + (size_t)i0 * HID + lane * 4);
            const float ev = __expf(lrelu2(es + ev0d));
            const float2 f01 = bf2f(xs.x), f23 = bf2f(xs.y);
            a0.x += f01.x * ev; a0.y += f01.y * ev;
            a0.z += f23.x * ev; a0.w += f23.y * ev;
            den0 += ev;
            s0++;
        }
        if (p1) {
            const float es = __ldg(&g_es2[i1]);
            const uint2 xs = *(const uint2*)(g_xw2b + (size_t)i1 * HID + lane * 4);
            const float ev = __expf(lrelu2(es + ev1d));
            const float2 f01 = bf2f(xs.x), f23 = bf2f(xs.y);
            a1.x += f01.x * ev; a1.y += f01.y * ev;
            a1.z += f23.x * ev; a1.w += f23.y * ev;
            den1 += ev;
            s1++;
        }
    }
    const float4 b = ((const float4*)g2b)[lane];
    {
        const float inv = 1.f / den0;
        float4 o;
        o.x = a0.x * inv + b.x; o.y = a0.y * inv + b.y;
        o.z = a0.z * inv + b.z; o.w = a0.w * inv + b.w;
        *(float4*)(g_out2 + (size_t)d0 * HID + lane * 4) = o;
    }
    if (d1 < NN) {
        const float inv = 1.f / den1;
        float4 o;
        o.x = a1.x * inv + b.x; o.y = a1.y * inv + b.y;
        o.z = a1.z * inv + b.z; o.w = a1.w * inv + b.w;
        *(float4*)(g_out2 + (size_t)d1 * HID + lane * 4) = o;
    }
}

// ---------------- output head ------------------------------------------------
__global__ void __launch_bounds__(128) k_final(
    const float* __restrict__ bo1, const float* __restrict__ Wo2,
    const float* __restrict__ bo2, float* __restrict__ out)
{
    __shared__ __align__(16) __nv_bfloat16 ab[128 * XS];
    __shared__ float sp[2][4][NT];
    const int tid = threadIdx.x, n0 = blockIdx.x * NT;
    const int wid = tid >> 5, lane = tid & 31;
    const int lr = lane >> 2, lq2 = (lane & 3) * 2;

    for (int i = 0; i < 16; i++) {
        const int idx = tid + i * 128;
        const int node = idx >> 5, c4 = idx & 31;
        int gr = n0 + node; if (gr >= NN) gr = NN - 1;
        const float4 v = *(const float4*)(g_out2 + (size_t)gr * HID + 4 * c4);
        uint2 h, l;
        split4(v, h, l);
        *(uint2*)(ab + node * XS + 4 * c4) = h;
        *(uint2*)(ab + (64 + node) * XS + 4 * c4) = l;
    }
    __syncthreads();

    float c[4][4][4];
#pragma unroll
    for (int m = 0; m < 4; m++)
#pragma unroll
        for (int nt = 0; nt < 4; nt++)
#pragma unroll
            for (int q = 0; q < 4; q++) c[m][nt][q] = 0.f;
    mma_gemmT<4>(ab, g_Wo1p, wid, lane, c);

    float p0[4][2], p1[4][2];
#pragma unroll
    for (int m = 0; m < 4; m++) { p0[m][0]=p0[m][1]=p1[m][0]=p1[m][1]=0.f; }
#pragma unroll
    for (int m = 0; m < 4; m++)
#pragma unroll
        for (int nt = 0; nt < 4; nt++) {
            const int cb = wid * 32 + nt * 8 + lq2;
            const float b0 = bo1[cb], b1 = bo1[cb + 1];
            const float w00 = Wo2[cb], w01 = Wo2[cb + 1];
            const float w10 = Wo2[128 + cb], w11 = Wo2[128 + cb + 1];
            const float y00 = lrelu01(c[m][nt][0] + b0), y01 = lrelu01(c[m][nt][1] + b1);
            const float y10 = lrelu01(c[m][nt][2] + b0), y11 = lrelu01(c[m][nt][3] + b1);
            p0[m][0] += y00*w00 + y01*w01;  p0[m][1] += y10*w00 + y11*w01;
            p1[m][0] += y00*w10 + y01*w11;  p1[m][1] += y10*w10 + y11*w11;
        }
#pragma unroll
    for (int m = 0; m < 4; m++)
#pragma unroll
        for (int rr = 0; rr < 2; rr++) {
#pragma unroll
            for (int o = 1; o < 4; o <<= 1) {
                p0[m][rr] += __shfl_xor_sync(0xffffffffu, p0[m][rr], o);
                p1[m][rr] += __shfl_xor_sync(0xffffffffu, p1[m][rr], o);
            }
        }
    if ((lane & 3) == 0) {
#pragma unroll
        for (int m = 0; m < 4; m++) {
            sp[0][wid][m * 16 + lr]     = p0[m][0];
            sp[0][wid][m * 16 + lr + 8] = p0[m][1];
            sp[1][wid][m * 16 + lr]     = p1[m][0];
            sp[1][wid][m * 16 + lr + 8] = p1[m][1];
        }
    }
    __syncthreads();
    if (tid < NT) {
        if (n0 + tid < NN)
            out[(size_t)(n0 + tid) * 2] =
                sp[0][0][tid] + sp[0][1][tid] + sp[0][2][tid] + sp[0][3][tid] + bo2[0];
    } else {
        const int m = tid - NT;
        if (n0 + m < NN)
            out[(size_t)(n0 + m) * 2 + 1] =
                sp[1][0][m] + sp[1][1][m] + sp[1][2][m] + sp[1][3][m] + bo2[1];
    }
}

// ---------------- launch ------------------------------------------------------
extern "C" void kernel_launch(void* const* d_in, const int* in_sizes, int n_in,
                              void* d_out, int out_size) {
    const float* des  = (const float*)d_in[0];
    const float* twt  = (const float*)d_in[1];
    const float* npr  = (const float*)d_in[2];
    const float* cpr  = (const float*)d_in[3];
    const int*   ei   = (const int*)d_in[4];   // JAX x64 disabled -> int32
    const float* Wd = (const float*)d_in[5];   const float* bd = (const float*)d_in[6];
    const float* Wt = (const float*)d_in[7];   const float* bt = (const float*)d_in[8];
    const float* Wn = (const float*)d_in[9];   const float* bn = (const float*)d_in[10];
    const float* Wc = (const float*)d_in[11];  const float* bc = (const float*)d_in[12];
    const float* Wi = (const float*)d_in[13];  const float* bi = (const float*)d_in[14];
    const float* g1W  = (const float*)d_in[15];
    const float* g1as = (const float*)d_in[16];
    const float* g1ad = (const float*)d_in[17];
    const float* g1b  = (const float*)d_in[18];
    const float* g2W  = (const float*)d_in[19];
    const float* g2as = (const float*)d_in[20];
    const float* g2ad = (const float*)d_in[21];
    const float* g2b  = (const float*)d_in[22];
    const float* Wo1  = (const float*)d_in[23]; const float* bo1 = (const float*)d_in[24];
    const float* Wo2  = (const float*)d_in[25]; const float* bo2 = (const float*)d_in[26];
    float* out = (float*)d_out;

    const int NB = (NN + NT - 1) / NT;          // 1563 node blocks
    const int AGB = ((NN + 1) / 2 * 32 + 255) / 256;  // dual-dst agg blocks
    k_wprep<<<(NN + 255) / 256, 256>>>(Wd, Wt, Wi, g1W, g2W, Wo1);  // + cnt init
    k_count<<<(EE + 255) / 256, 256>>>(ei);
    k_scan1<<<SCB, 256>>>();
    k_features<<<NB, 128>>>(des, twt, npr, cpr, bd, bt, Wn, bn, Wc, bc,
                            bi, g1as, g1ad);          // ncu-captured slot (idx 3)
    k_scan2<<<1, 32>>>();
    k_scan3<<<SCB, 256>>>();
    k_fill<<<(ET + 255) / 256, 256>>>(ei);
    k_agg1<<<AGB, 256>>>(g1b);
    k_gat2_prep<<<NB, 128>>>(g2as, g2ad);
    k_agg2<<<AGB, 256>>>(g2b);
    k_final<<<NB, 128>>>(bo1, Wo2, bo2, out);
}

// round 17
// speedup vs baseline: 1.1278x; 1.1278x over previous
#include <cuda_runtime.h>
#include <cuda_bf16.h>

#define NN   100000
#define EE   1600000
#define ET   (EE + NN)
#define HID  128
#define NT   64                 // nodes per block (node kernels)
#define XS   136                // bf16 activation row stride (k=128 + pad)
#define SCB  100                // scan blocks
#define SCL  1000               // nodes per scan block

// ---------------- scratch globals --------------------------------------------
__device__ __align__(16) __nv_bfloat16 g_xw1b[(size_t)NN * HID]; // xw1 bf16
__device__ __align__(16) __nv_bfloat16 g_xw2b[(size_t)NN * HID]; // xw2 bf16
__device__ __align__(16) float g_es1 [NN * 4];
__device__ __align__(16) float g_ed1 [NN * 4];
__device__ __align__(16) float g_out1[(size_t)NN * HID];
__device__ __align__(16) float g_es2 [NN];
__device__ __align__(16) float g_ed2 [NN];
__device__ __align__(16) float g_out2[(size_t)NN * HID];

// fragment-packed weights: [col][kstep][quad] -> 16B {hi01,hi89,lo01,lo89}
__device__ __align__(16) __nv_bfloat16 g_W1p [64 * 48 * 4 * 8];
__device__ __align__(16) __nv_bfloat16 g_Wip [128 * 8 * 4 * 8];
__device__ __align__(16) __nv_bfloat16 g_g1p [128 * 8 * 4 * 8];
__device__ __align__(16) __nv_bfloat16 g_g2p [128 * 8 * 4 * 8];
__device__ __align__(16) __nv_bfloat16 g_Wo1p[128 * 8 * 4 * 8];

// CSR (dst-grouped)
__device__ int g_cnt[NN];
__device__ int g_rs [NN + 1];
__device__ int g_cur[NN];
__device__ int g_csrc[ET];
__device__ int g_part[SCB];

__device__ __forceinline__ float lrelu01(float v) { return v > 0.f ? v : 0.01f * v; }
__device__ __forceinline__ float lrelu2 (float v) { return v > 0.f ? v : 0.2f  * v; }

__device__ __forceinline__ unsigned cvta_s(const void* p) {
    return (unsigned)__cvta_generic_to_shared(p);
}
__device__ __forceinline__ void ldm_x4(uint4& v, unsigned addr) {
    asm volatile("ldmatrix.sync.aligned.m8n8.x4.shared.b16 {%0,%1,%2,%3}, [%4];"
                 : "=r"(v.x), "=r"(v.y), "=r"(v.z), "=r"(v.w) : "r"(addr));
}
__device__ __forceinline__ void mma_bf16(float c[4], const uint4& a,
                                         unsigned b0, unsigned b1) {
    asm volatile(
        "mma.sync.aligned.m16n8k16.row.col.f32.bf16.bf16.f32 "
        "{%0,%1,%2,%3},{%4,%5,%6,%7},{%8,%9},{%0,%1,%2,%3};"
        : "+f"(c[0]), "+f"(c[1]), "+f"(c[2]), "+f"(c[3])
        : "r"(a.x), "r"(a.y), "r"(a.z), "r"(a.w), "r"(b0), "r"(b1));
}

// f32x2 -> bf16x2 hi + lo
__device__ __forceinline__ void cvt2(float2 v, unsigned& h, unsigned& l) {
    __nv_bfloat162 hb = __float22bfloat162_rn(v);
    h = *(unsigned*)&hb;
    const float2 hf = __bfloat1622float2(hb);
    __nv_bfloat162 lb = __float22bfloat162_rn(make_float2(v.x - hf.x, v.y - hf.y));
    l = *(unsigned*)&lb;
}
__device__ __forceinline__ void split4(float4 v, uint2& h, uint2& l) {
    cvt2(make_float2(v.x, v.y), h.x, l.x);
    cvt2(make_float2(v.z, v.w), h.y, l.y);
}
__device__ __forceinline__ unsigned pack_bf2(float a, float b) {
    __nv_bfloat162 t = __halves2bfloat162(__float2bfloat16(a), __float2bfloat16(b));
    return *(unsigned*)&t;
}
__device__ __forceinline__ float2 bf2f(unsigned u) {
    float2 r;
    r.x = __uint_as_float(u << 16);
    r.y = __uint_as_float(u & 0xffff0000u);
    return r;
}

// 3-term bf16 GEMM: MT*16 nodes x 32 cols (per warp) x K=128.
template <int MT>
__device__ __forceinline__ void mma_gemmT(const __nv_bfloat16* abuf,
                                          const __nv_bfloat16* __restrict__ wp,
                                          int wid, int lane, float c[MT][4][4]) {
    const int row_l = (lane & 7) + ((lane >> 3) & 1) * 8;
    const int koff  = (lane >> 4) * 8;
    const int nrow  = lane >> 2, q = lane & 3;
    const unsigned sb = cvta_s(abuf);
    const int LO = MT * 16;
#pragma unroll
    for (int ks = 0; ks < 8; ks++) {
        uint4 ah[MT], al[MT];
#pragma unroll
        for (int m = 0; m < MT; m++) {
            ldm_x4(ah[m], sb + ((m * 16 + row_l) * XS + ks * 16 + koff) * 2);
            ldm_x4(al[m], sb + ((LO + m * 16 + row_l) * XS + ks * 16 + koff) * 2);
        }
#pragma unroll
        for (int nt = 0; nt < 4; nt++) {
            const int col = wid * 32 + nt * 8 + nrow;
            const uint4 b = *(const uint4*)(wp + ((size_t)(col * 8 + ks) * 4 + q) * 8);
#pragma unroll
            for (int m = 0; m < MT; m++) {
                mma_bf16(c[m][nt], ah[m], b.x, b.y);
                mma_bf16(c[m][nt], ah[m], b.z, b.w);
                mma_bf16(c[m][nt], al[m], b.x, b.y);
            }
        }
    }
}

// ---------------- weight prep + cnt init --------------------------------------
__device__ __forceinline__ uint4 pack_frag(float v0, float v1, float v2, float v3) {
    uint4 r; uint2 h, l;
    cvt2(make_float2(v0, v1), h.x, l.x);
    cvt2(make_float2(v2, v3), h.y, l.y);
    r.x = h.x; r.y = h.y; r.z = l.x; r.w = l.y;
    return r;
}

__global__ void k_wprep(const float* __restrict__ Wd, const float* __restrict__ Wt,
                        const float* __restrict__ Wi, const float* __restrict__ g1W,
                        const float* __restrict__ g2W, const float* __restrict__ Wo1) {
    const int i = blockIdx.x * blockDim.x + threadIdx.x;
    if (i < NN) g_cnt[i] = 1;
    if (i < 64 * 48 * 4) {
        const int col = i / 192, ks = (i % 192) / 4, q = i % 4;
        const int k0 = ks * 16 + q * 2;
        const float* src = (col < 32) ? Wd + (size_t)col * 768
                                      : Wt + (size_t)(col - 32) * 768;
        *(uint4*)(g_W1p + (size_t)i * 8) =
            pack_frag(src[k0], src[k0 + 1], src[k0 + 8], src[k0 + 9]);
    } else if (i < 64 * 48 * 4 + 4 * 128 * 8 * 4) {
        const int j = i - 64 * 48 * 4;
        const int mat = j >> 12, r = j & 4095;
        const int col = r / 32, ks = (r % 32) / 4, q = r % 4;
        const int k0 = ks * 16 + q * 2;
        const float* W = (mat == 0 ? Wi : mat == 1 ? g1W : mat == 2 ? g2W : Wo1)
                       + (size_t)col * 128;
        __nv_bfloat16* dst = (mat == 0 ? g_Wip : mat == 1 ? g_g1p
                              : mat == 2 ? g_g2p : g_Wo1p);
        *(uint4*)(dst + (size_t)r * 8) =
            pack_frag(W[k0], W[k0 + 1], W[k0 + 8], W[k0 + 9]);
    }
}

// ---------------- CSR build ---------------------------------------------------
__global__ void k_count(const int* __restrict__ ei) {
    int i = blockIdx.x * blockDim.x + threadIdx.x;
    if (i < EE) atomicAdd(&g_cnt[ei[EE + i]], 1);
}
__global__ void k_scan1() {
    __shared__ int sh[256];
    const int b = blockIdx.x, t = threadIdx.x;
    const int base = b * SCL;
    int s = 0;
    for (int i = t; i < SCL; i += 256) s += g_cnt[base + i];
    sh[t] = s;
    __syncthreads();
    for (int o = 128; o > 0; o >>= 1) {
        if (t < o) sh[t] += sh[t + o];
        __syncthreads();
    }
    if (t == 0) g_part[b] = sh[0];
}
__global__ void k_scan2() {
    if (threadIdx.x == 0) {
        int acc = 0;
        for (int i = 0; i < SCB; i++) { int v = g_part[i]; g_part[i] = acc; acc += v; }
        g_rs[NN] = ET;
    }
}
__global__ void k_scan3() {
    __shared__ int sh[256];
    const int b = blockIdx.x, t = threadIdx.x;
    const int base = b * SCL;
    int loc[4];
    int s = 0;
#pragma unroll
    for (int j = 0; j < 4; j++) {
        const int idx = t * 4 + j;
        loc[j] = (idx < SCL) ? g_cnt[base + idx] : 0;
        s += loc[j];
    }
    sh[t] = s;
    __syncthreads();
    for (int o = 1; o < 256; o <<= 1) {
        int v = (t >= o) ? sh[t - o] : 0;
        __syncthreads();
        sh[t] += v;
        __syncthreads();
    }
    int pre = g_part[b] + (t ? sh[t - 1] : 0);
#pragma unroll
    for (int j = 0; j < 4; j++) {
        const int idx = t * 4 + j;
        if (idx < SCL) {
            g_rs[base + idx] = pre;
            g_cur[base + idx] = pre;
            pre += loc[j];
        }
    }
}
__global__ void k_fill(const int* __restrict__ ei) {
    int i = blockIdx.x * blockDim.x + threadIdx.x;
    if (i >= ET) return;
    int src, dst;
    if (i < EE) { src = ei[i]; dst = ei[EE + i]; }
    else        { src = dst = i - EE; }
    g_csrc[atomicAdd(&g_cur[dst], 1)] = src;
}

// ---------------- features -> x -> Wi -> g1 projection + attn logits ---------
__global__ void __launch_bounds__(128, 4) k_features(
    const float* __restrict__ des, const float* __restrict__ twt,
    const float* __restrict__ npr, const float* __restrict__ cpr,
    const float* __restrict__ bd,  const float* __restrict__ bt,
    const float* __restrict__ Wn,  const float* __restrict__ bn,
    const float* __restrict__ Wc,  const float* __restrict__ bc,
    const float* __restrict__ bi,
    const float* __restrict__ g1as, const float* __restrict__ g1ad)
{
    __shared__ __align__(16) __nv_bfloat16 xb[128 * XS];   // hi rows 0-63, lo 64-127

    const int tid = threadIdx.x;
    const int n0  = blockIdx.x * NT;
    const int wid = tid >> 5, lane = tid & 31;
    const int lr = lane >> 2, lq = lane & 3, lq2 = lq * 2;

    // ---- stage 1: register-prefetched fragments, warp = (arr, node-half) ----
    const int arr = wid & 1;
    const int mh  = wid >> 1;            // nodes mh*32 .. mh*32+31

    float c1[2][4][4];
#pragma unroll
    for (int m = 0; m < 2; m++)
#pragma unroll
        for (int nt = 0; nt < 4; nt++)
#pragma unroll
            for (int q = 0; q < 4; q++) c1[m][nt][q] = 0.f;

    {
        const float* A = arr ? twt : des;
        const float* rp[2][2];
#pragma unroll
        for (int m = 0; m < 2; m++) {
            int r0 = n0 + mh * 32 + m * 16 + lr;
            int r1 = r0 + 8;
            if (r0 >= NN) r0 = NN - 1;
            if (r1 >= NN) r1 = NN - 1;
            rp[m][0] = A + (size_t)r0 * 768 + lq2;
            rp[m][1] = A + (size_t)r1 * 768 + lq2;
        }
        // prefetch chunk 0
        float2 cur[2][4];
#pragma unroll
        for (int m = 0; m < 2; m++) {
            cur[m][0] = *(const float2*)(rp[m][0]);
            cur[m][1] = *(const float2*)(rp[m][1]);
            cur[m][2] = *(const float2*)(rp[m][0] + 8);
            cur[m][3] = *(const float2*)(rp[m][1] + 8);
        }
#pragma unroll 2
        for (int ks = 0; ks < 48; ks++) {
            float2 nxt[2][4];
            if (ks < 47) {
                const int kk = (ks + 1) * 16;
#pragma unroll
                for (int m = 0; m < 2; m++) {
                    nxt[m][0] = *(const float2*)(rp[m][0] + kk);
                    nxt[m][1] = *(const float2*)(rp[m][1] + kk);
                    nxt[m][2] = *(const float2*)(rp[m][0] + kk + 8);
                    nxt[m][3] = *(const float2*)(rp[m][1] + kk + 8);
                }
            }
            uint4 ah[2], al[2];
#pragma unroll
            for (int m = 0; m < 2; m++) {
                cvt2(cur[m][0], ah[m].x, al[m].x);
                cvt2(cur[m][1], ah[m].y, al[m].y);
                cvt2(cur[m][2], ah[m].z, al[m].z);
                cvt2(cur[m][3], ah[m].w, al[m].w);
            }
#pragma unroll
            for (int nt = 0; nt < 4; nt++) {
                const int col = arr * 32 + nt * 8 + lr;
                const uint4 b = *(const uint4*)(g_W1p +
                    ((size_t)(col * 48 + ks) * 4 + lq) * 8);
#pragma unroll
                for (int m = 0; m < 2; m++) {
                    mma_bf16(c1[m][nt], ah[m], b.x, b.y);
                    mma_bf16(c1[m][nt], ah[m], b.z, b.w);
                    mma_bf16(c1[m][nt], al[m], b.x, b.y);
                }
            }
#pragma unroll
            for (int m = 0; m < 2; m++) {
                cur[m][0] = nxt[m][0]; cur[m][1] = nxt[m][1];
                cur[m][2] = nxt[m][2]; cur[m][3] = nxt[m][3];
            }
        }
    }

    // ---- stage-1 epilogue: bias + lrelu -> xb hi/lo [node][col] -------------
#pragma unroll
    for (int m = 0; m < 2; m++)
#pragma unroll
        for (int nt = 0; nt < 4; nt++) {
            const int cb = arr * 32 + nt * 8 + lq2;
            const float b0 = (cb < 32) ? bd[cb] : bt[cb - 32];
            const float b1 = (cb + 1 < 32) ? bd[cb + 1] : bt[cb - 31];
            const int r0 = mh * 32 + m * 16 + lr;
            const float v00 = lrelu01(c1[m][nt][0] + b0), v01 = lrelu01(c1[m][nt][1] + b1);
            const float v10 = lrelu01(c1[m][nt][2] + b0), v11 = lrelu01(c1[m][nt][3] + b1);
            *(unsigned*)(xb + r0 * XS + cb)        = pack_bf2(v00, v01);
            *(unsigned*)(xb + (64 + r0) * XS + cb) = pack_bf2(
                v00 - __bfloat162float(__float2bfloat16(v00)),
                v01 - __bfloat162float(__float2bfloat16(v01)));
            *(unsigned*)(xb + (r0 + 8) * XS + cb)  = pack_bf2(v10, v11);
            *(unsigned*)(xb + (72 + r0) * XS + cb) = pack_bf2(
                v10 - __bfloat162float(__float2bfloat16(v10)),
                v11 - __bfloat162float(__float2bfloat16(v11)));
        }
    {   // num/cat cols 64-127 over 64 nodes
        const int col = tid >> 1, nh = (tid & 1) * 32;
        if (col < 32) {
            const float w0 = Wn[col * 5], w1 = Wn[col * 5 + 1], w2 = Wn[col * 5 + 2],
                        w3 = Wn[col * 5 + 3], w4 = Wn[col * 5 + 4];
            const float b = bn[col];
            for (int m = 0; m < 32; m++) {
                int gr = n0 + nh + m; if (gr >= NN) gr = NN - 1;
                const float* r = npr + (size_t)gr * 5;
                const float v = lrelu01(r[0]*w0 + r[1]*w1 + r[2]*w2 + r[3]*w3 + r[4]*w4 + b);
                const __nv_bfloat16 h = __float2bfloat16(v);
                xb[(nh + m) * XS + 64 + col] = h;
                xb[(64 + nh + m) * XS + 64 + col] = __float2bfloat16(v - __bfloat162float(h));
            }
        } else {
            const int jj = col - 32;
            const float w0 = Wc[jj * 3], w1 = Wc[jj * 3 + 1], w2 = Wc[jj * 3 + 2];
            const float b = bc[jj];
            for (int m = 0; m < 32; m++) {
                int gr = n0 + nh + m; if (gr >= NN) gr = NN - 1;
                const float* r = cpr + (size_t)gr * 3;
                const float v = lrelu01(r[0]*w0 + r[1]*w1 + r[2]*w2 + b);
                const __nv_bfloat16 h = __float2bfloat16(v);
                xb[(nh + m) * XS + 96 + jj] = h;
                xb[(64 + nh + m) * XS + 96 + jj] = __float2bfloat16(v - __bfloat162float(h));
            }
        }
    }
    __syncthreads();

    // ---- stage 2: x2 = lrelu(x @ Wi^T + bi), write back into xb -------------
    {
        float c[4][4][4];
#pragma unroll
        for (int m = 0; m < 4; m++)
#pragma unroll
            for (int nt = 0; nt < 4; nt++)
#pragma unroll
                for (int q = 0; q < 4; q++) c[m][nt][q] = 0.f;
        mma_gemmT<4>(xb, g_Wip, wid, lane, c);
        __syncthreads();
#pragma unroll
        for (int m = 0; m < 4; m++)
#pragma unroll
            for (int nt = 0; nt < 4; nt++) {
                const int cb = wid * 32 + nt * 8 + lq2;
                const float b0 = bi[cb], b1 = bi[cb + 1];
                const int r0 = m * 16 + lr;
                const float v00 = lrelu01(c[m][nt][0] + b0), v01 = lrelu01(c[m][nt][1] + b1);
                const float v10 = lrelu01(c[m][nt][2] + b0), v11 = lrelu01(c[m][nt][3] + b1);
                *(unsigned*)(xb + r0 * XS + cb)        = pack_bf2(v00, v01);
                *(unsigned*)(xb + (64 + r0) * XS + cb) = pack_bf2(
                    v00 - __bfloat162float(__float2bfloat16(v00)),
                    v01 - __bfloat162float(__float2bfloat16(v01)));
                *(unsigned*)(xb + (r0 + 8) * XS + cb)  = pack_bf2(v10, v11);
                *(unsigned*)(xb + (72 + r0) * XS + cb) = pack_bf2(
                    v10 - __bfloat162float(__float2bfloat16(v10)),
                    v11 - __bfloat162float(__float2bfloat16(v11)));
            }
    }
    __syncthreads();

    // ---- stage 3: xw1 = x2 @ g1_W^T + per-head logits; xw1 stored bf16 ------
    {
        float c[4][4][4];
#pragma unroll
        for (int m = 0; m < 4; m++)
#pragma unroll
            for (int nt = 0; nt < 4; nt++)
#pragma unroll
                for (int q = 0; q < 4; q++) c[m][nt][q] = 0.f;
        mma_gemmT<4>(xb, g_g1p, wid, lane, c);

        float ps[4][2], pd[4][2];
#pragma unroll
        for (int m = 0; m < 4; m++) { ps[m][0]=ps[m][1]=pd[m][0]=pd[m][1]=0.f; }
#pragma unroll
        for (int m = 0; m < 4; m++)
#pragma unroll
            for (int nt = 0; nt < 4; nt++) {
                const int cb = wid * 32 + nt * 8 + lq2;
                const int node = n0 + m * 16 + lr;
                if (node < NN)
                    *(unsigned*)(g_xw1b + (size_t)node * HID + cb) =
                        pack_bf2(c[m][nt][0], c[m][nt][1]);
                if (node + 8 < NN)
                    *(unsigned*)(g_xw1b + (size_t)(node + 8) * HID + cb) =
                        pack_bf2(c[m][nt][2], c[m][nt][3]);
                const float a0 = g1as[cb], a1 = g1as[cb + 1];
                const float d0 = g1ad[cb], d1 = g1ad[cb + 1];
                ps[m][0] += c[m][nt][0]*a0 + c[m][nt][1]*a1;
                ps[m][1] += c[m][nt][2]*a0 + c[m][nt][3]*a1;
                pd[m][0] += c[m][nt][0]*d0 + c[m][nt][1]*d1;
                pd[m][1] += c[m][nt][2]*d0 + c[m][nt][3]*d1;
            }
#pragma unroll
        for (int m = 0; m < 4; m++)
#pragma unroll
            for (int rr = 0; rr < 2; rr++) {
#pragma unroll
                for (int o = 1; o < 4; o <<= 1) {
                    ps[m][rr] += __shfl_xor_sync(0xffffffffu, ps[m][rr], o);
                    pd[m][rr] += __shfl_xor_sync(0xffffffffu, pd[m][rr], o);
                }
            }
        if ((lane & 3) == 0) {
#pragma unroll
            for (int m = 0; m < 4; m++) {
                const int node = n0 + m * 16 + lr;
                if (node < NN) {
                    g_es1[node * 4 + wid] = ps[m][0];
                    g_ed1[node * 4 + wid] = pd[m][0];
                }
                if (node + 8 < NN) {
                    g_es1[(node + 8) * 4 + wid] = ps[m][1];
                    g_ed1[(node + 8) * 4 + wid] = pd[m][1];
                }
            }
        }
    }
}

// ---------------- GAT1 aggregation: bf16 gather, fused exp --------------------
__global__ void __launch_bounds__(256) k_agg1(const float* __restrict__ g1b) {
    const int d = (blockIdx.x * blockDim.x + threadIdx.x) >> 5;
    const int lane = threadIdx.x & 31;
    if (d >= NN) return;
    const int beg = g_rs[d], end = g_rs[d + 1];
    const int h = lane >> 3;
    const float edv = g_ed1[d * 4 + h];
    float4 acc = {0.f, 0.f, 0.f, 0.f};
    float den = 0.f;
#pragma unroll 2
    for (int s = beg; s < end; s++) {
        const int src = __ldg(&g_csrc[s]);
        const float es = __ldg(&g_es1[src * 4 + h]);
        const float ev = __expf(lrelu2(es + edv));
        const uint2 xs = *(const uint2*)(g_xw1b + (size_t)src * HID + lane * 4);
        const float2 f01 = bf2f(xs.x), f23 = bf2f(xs.y);
        acc.x += f01.x * ev; acc.y += f01.y * ev;
        acc.z += f23.x * ev; acc.w += f23.y * ev;
        den += ev;
    }
    const float inv = 1.f / den;
    const float4 b = ((const float4*)g1b)[lane];
    float4 o;
    o.x = acc.x * inv + b.x; o.y = acc.y * inv + b.y;
    o.z = acc.z * inv + b.z; o.w = acc.w * inv + b.w;
    *(float4*)(g_out1 + (size_t)d * HID + lane * 4) = o;
}

// ---------------- GAT2 projection + attn logits -------------------------------
__global__ void __launch_bounds__(128) k_gat2_prep(
    const float* __restrict__ g2as, const float* __restrict__ g2ad)
{
    __shared__ __align__(16) __nv_bfloat16 ab[128 * XS];
    __shared__ float sp[2][4][NT];
    const int tid = threadIdx.x, n0 = blockIdx.x * NT;
    const int wid = tid >> 5, lane = tid & 31;
    const int lr = lane >> 2, lq2 = (lane & 3) * 2;

    for (int i = 0; i < 16; i++) {
        const int idx = tid + i * 128;
        const int node = idx >> 5, c4 = idx & 31;
        int gr = n0 + node; if (gr >= NN) gr = NN - 1;
        const float4 v = *(const float4*)(g_out1 + (size_t)gr * HID + 4 * c4);
        uint2 h, l;
        split4(v, h, l);
        *(uint2*)(ab + node * XS + 4 * c4) = h;
        *(uint2*)(ab + (64 + node) * XS + 4 * c4) = l;
    }
    __syncthreads();

    float c[4][4][4];
#pragma unroll
    for (int m = 0; m < 4; m++)
#pragma unroll
        for (int nt = 0; nt < 4; nt++)
#pragma unroll
            for (int q = 0; q < 4; q++) c[m][nt][q] = 0.f;
    mma_gemmT<4>(ab, g_g2p, wid, lane, c);

    float ps[4][2], pd[4][2];
#pragma unroll
    for (int m = 0; m < 4; m++) { ps[m][0]=ps[m][1]=pd[m][0]=pd[m][1]=0.f; }
#pragma unroll
    for (int m = 0; m < 4; m++)
#pragma unroll
        for (int nt = 0; nt < 4; nt++) {
            const int cb = wid * 32 + nt * 8 + lq2;
            const int node = n0 + m * 16 + lr;
            if (node < NN)
                *(unsigned*)(g_xw2b + (size_t)node * HID + cb) =
                    pack_bf2(c[m][nt][0], c[m][nt][1]);
            if (node + 8 < NN)
                *(unsigned*)(g_xw2b + (size_t)(node + 8) * HID + cb) =
                    pack_bf2(c[m][nt][2], c[m][nt][3]);
            const float a0 = g2as[cb], a1 = g2as[cb + 1];
            const float d0 = g2ad[cb], d1 = g2ad[cb + 1];
            ps[m][0] += c[m][nt][0]*a0 + c[m][nt][1]*a1;
            ps[m][1] += c[m][nt][2]*a0 + c[m][nt][3]*a1;
            pd[m][0] += c[m][nt][0]*d0 + c[m][nt][1]*d1;
            pd[m][1] += c[m][nt][2]*d0 + c[m][nt][3]*d1;
        }
#pragma unroll
    for (int m = 0; m < 4; m++)
#pragma unroll
        for (int rr = 0; rr < 2; rr++) {
#pragma unroll
            for (int o = 1; o < 4; o <<= 1) {
                ps[m][rr] += __shfl_xor_sync(0xffffffffu, ps[m][rr], o);
                pd[m][rr] += __shfl_xor_sync(0xffffffffu, pd[m][rr], o);
            }
        }
    if ((lane & 3) == 0) {
#pragma unroll
        for (int m = 0; m < 4; m++) {
            sp[0][wid][m * 16 + lr]     = ps[m][0];
            sp[0][wid][m * 16 + lr + 8] = ps[m][1];
            sp[1][wid][m * 16 + lr]     = pd[m][0];
            sp[1][wid][m * 16 + lr + 8] = pd[m][1];
        }
    }
    __syncthreads();
    if (tid < NT) {
        if (n0 + tid < NN)
            g_es2[n0 + tid] = sp[0][0][tid] + sp[0][1][tid] + sp[0][2][tid] + sp[0][3][tid];
    } else {
        const int m = tid - NT;
        if (n0 + m < NN)
            g_ed2[n0 + m] = sp[1][0][m] + sp[1][1][m] + sp[1][2][m] + sp[1][3][m];
    }
}

// ---------------- GAT2 aggregation --------------------------------------------
__global__ void __launch_bounds__(256) k_agg2(const float* __restrict__ g2b) {
    const int d = (blockIdx.x * blockDim.x + threadIdx.x) >> 5;
    const int lane = threadIdx.x & 31;
    if (d >= NN) return;
    const int beg = g_rs[d], end = g_rs[d + 1];
    const float edv = g_ed2[d];
    float4 acc = {0.f, 0.f, 0.f, 0.f};
    float den = 0.f;
#pragma unroll 2
    for (int s = beg; s < end; s++) {
        const int src = __ldg(&g_csrc[s]);
        const float es = __ldg(&g_es2[src]);
        const float ev = __expf(lrelu2(es + edv));
        const uint2 xs = *(const uint2*)(g_xw2b + (size_t)src * HID + lane * 4);
        const float2 f01 = bf2f(xs.x), f23 = bf2f(xs.y);
        acc.x += f01.x * ev; acc.y += f01.y * ev;
        acc.z += f23.x * ev; acc.w += f23.y * ev;
        den += ev;
    }
    const float inv = 1.f / den;
    const float4 b = ((const float4*)g2b)[lane];
    float4 o;
    o.x = acc.x * inv + b.x; o.y = acc.y * inv + b.y;
    o.z = acc.z * inv + b.z; o.w = acc.w * inv + b.w;
    *(float4*)(g_out2 + (size_t)d * HID + lane * 4) = o;
}

// ---------------- output head ------------------------------------------------
__global__ void __launch_bounds__(128) k_final(
    const float* __restrict__ bo1, const float* __restrict__ Wo2,
    const float* __restrict__ bo2, float* __restrict__ out)
{
    __shared__ __align__(16) __nv_bfloat16 ab[128 * XS];
    __shared__ float sp[2][4][NT];
    const int tid = threadIdx.x, n0 = blockIdx.x * NT;
    const int wid = tid >> 5, lane = tid & 31;
    const int lr = lane >> 2, lq2 = (lane & 3) * 2;

    for (int i = 0; i < 16; i++) {
        const int idx = tid + i * 128;
        const int node = idx >> 5, c4 = idx & 31;
        int gr = n0 + node; if (gr >= NN) gr = NN - 1;
        const float4 v = *(const float4*)(g_out2 + (size_t)gr * HID + 4 * c4);
        uint2 h, l;
        split4(v, h, l);
        *(uint2*)(ab + node * XS + 4 * c4) = h;
        *(uint2*)(ab + (64 + node) * XS + 4 * c4) = l;
    }
    __syncthreads();

    float c[4][4][4];
#pragma unroll
    for (int m = 0; m < 4; m++)
#pragma unroll
        for (int nt = 0; nt < 4; nt++)
#pragma unroll
            for (int q = 0; q < 4; q++) c[m][nt][q] = 0.f;
    mma_gemmT<4>(ab, g_Wo1p, wid, lane, c);

    float p0[4][2], p1[4][2];
#pragma unroll
    for (int m = 0; m < 4; m++) { p0[m][0]=p0[m][1]=p1[m][0]=p1[m][1]=0.f; }
#pragma unroll
    for (int m = 0; m < 4; m++)
#pragma unroll
        for (int nt = 0; nt < 4; nt++) {
            const int cb = wid * 32 + nt * 8 + lq2;
            const float b0 = bo1[cb], b1 = bo1[cb + 1];
            const float w00 = Wo2[cb], w01 = Wo2[cb + 1];
            const float w10 = Wo2[128 + cb], w11 = Wo2[128 + cb + 1];
            const float y00 = lrelu01(c[m][nt][0] + b0), y01 = lrelu01(c[m][nt][1] + b1);
            const float y10 = lrelu01(c[m][nt][2] + b0), y11 = lrelu01(c[m][nt][3] + b1);
            p0[m][0] += y00*w00 + y01*w01;  p0[m][1] += y10*w00 + y11*w01;
            p1[m][0] += y00*w10 + y01*w11;  p1[m][1] += y10*w10 + y11*w11;
        }
#pragma unroll
    for (int m = 0; m < 4; m++)
#pragma unroll
        for (int rr = 0; rr < 2; rr++) {
#pragma unroll
            for (int o = 1; o < 4; o <<= 1) {
                p0[m][rr] += __shfl_xor_sync(0xffffffffu, p0[m][rr], o);
                p1[m][rr] += __shfl_xor_sync(0xffffffffu, p1[m][rr], o);
            }
        }
    if ((lane & 3) == 0) {
#pragma unroll
        for (int m = 0; m < 4; m++) {
            sp[0][wid][m * 16 + lr]     = p0[m][0];
            sp[0][wid][m * 16 + lr + 8] = p0[m][1];
            sp[1][wid][m * 16 + lr]     = p1[m][0];
            sp[1][wid][m * 16 + lr + 8] = p1[m][1];
        }
    }
    __syncthreads();
    if (tid < NT) {
        if (n0 + tid < NN)
            out[(size_t)(n0 + tid) * 2] =
                sp[0][0][tid] + sp[0][1][tid] + sp[0][2][tid] + sp[0][3][tid] + bo2[0];
    } else {
        const int m = tid - NT;
        if (n0 + m < NN)
            out[(size_t)(n0 + m) * 2 + 1] =
                sp[1][0][m] + sp[1][1][m] + sp[1][2][m] + sp[1][3][m] + bo2[1];
    }
}

// ---------------- launch ------------------------------------------------------
extern "C" void kernel_launch(void* const* d_in, const int* in_sizes, int n_in,
                              void* d_out, int out_size) {
    const float* des  = (const float*)d_in[0];
    const float* twt  = (const float*)d_in[1];
    const float* npr  = (const float*)d_in[2];
    const float* cpr  = (const float*)d_in[3];
    const int*   ei   = (const int*)d_in[4];   // JAX x64 disabled -> int32
    const float* Wd = (const float*)d_in[5];   const float* bd = (const float*)d_in[6];
    const float* Wt = (const float*)d_in[7];   const float* bt = (const float*)d_in[8];
    const float* Wn = (const float*)d_in[9];   const float* bn = (const float*)d_in[10];
    const float* Wc = (const float*)d_in[11];  const float* bc = (const float*)d_in[12];
    const float* Wi = (const float*)d_in[13];  const float* bi = (const float*)d_in[14];
    const float* g1W  = (const float*)d_in[15];
    const float* g1as = (const float*)d_in[16];
    const float* g1ad = (const float*)d_in[17];
    const float* g1b  = (const float*)d_in[18];
    const float* g2W  = (const float*)d_in[19];
    const float* g2as = (const float*)d_in[20];
    const float* g2ad = (const float*)d_in[21];
    const float* g2b  = (const float*)d_in[22];
    const float* Wo1  = (const float*)d_in[23]; const float* bo1 = (const float*)d_in[24];
    const float* Wo2  = (const float*)d_in[25]; const float* bo2 = (const float*)d_in[26];
    float* out = (float*)d_out;

    const int NB = (NN + NT - 1) / NT;        // 1563 node blocks
    k_wprep<<<(NN + 255) / 256, 256>>>(Wd, Wt, Wi, g1W, g2W, Wo1);  // + cnt init
    k_count<<<(EE + 255) / 256, 256>>>(ei);
    k_scan1<<<SCB, 256>>>();
    k_features<<<NB, 128>>>(des, twt, npr, cpr, bd, bt, Wn, bn, Wc, bc,
                            bi, g1as, g1ad);          // ncu-captured slot (idx 3)
    k_scan2<<<1, 32>>>();
    k_scan3<<<SCB, 256>>>();
    k_fill<<<(ET + 255) / 256, 256>>>(ei);
    k_agg1<<<(NN * 32 + 255) / 256, 256>>>(g1b);
    k_gat2_prep<<<NB, 128>>>(g2as, g2ad);
    k_agg2<<<(NN * 32 + 255) / 256, 256>>>(g2b);
    k_final<<<NB, 128>>>(bo1, Wo2, bo2, out);
}